// round 6
// baseline (speedup 1.0000x reference)
#include <cuda_runtime.h>
#include <mma.h>
#include <math.h>
#include <cstdint>

using namespace nvcuda;

#define D 128
#define MAX_N 100096
#define CAP 96
#define BROWS 128

// Scratch (allocation-free rule: __device__ globals).
__device__ float g_h[(size_t)MAX_N * D];          // SpMM accumulator
__device__ int   g_cnt[MAX_N];                    // per-node edge count
__device__ int2  g_edge[(size_t)MAX_N * CAP];     // edge buckets (src, w-bits)

// ---------------------------------------------------------------------------
__global__ void zero_kernel(int n) {
    int i = blockIdx.x * blockDim.x + threadIdx.x;
    if (i < n) g_cnt[i] = 0;
}

// ---------------------------------------------------------------------------
__global__ void scatter_kernel(const float* __restrict__ H,
                               const int*   __restrict__ src,
                               const int*   __restrict__ dst,
                               const float* __restrict__ ew,
                               int E) {
    int i = blockIdx.x * blockDim.x + threadIdx.x;
    if (i >= E) return;
    int d = dst[i];
    int pos = atomicAdd(&g_cnt[d], 1);
    int s = src[i];
    float w = ew[i];
    if (pos < CAP) {
        g_edge[(size_t)d * CAP + pos] = make_int2(s, __float_as_int(w));
    } else {
        // Statistically unreachable overflow; gather merges via cnt>CAP path.
        const float4* hp = (const float4*)(H + (size_t)s * D);
        float* o = g_h + (size_t)d * D;
        #pragma unroll 4
        for (int c = 0; c < D / 4; c++) {
            float4 v = __ldg(hp + c);
            asm volatile("red.global.add.v4.f32 [%0], {%1, %2, %3, %4};"
                         :: "l"(o + c * 4),
                            "f"(v.x * w), "f"(v.y * w), "f"(v.z * w), "f"(v.w * w)
                         : "memory");
        }
    }
}

// ---------------------------------------------------------------------------
__global__ __launch_bounds__(256)
void gather_kernel(const float* __restrict__ H, int N) {
    int warp = (int)((blockIdx.x * (unsigned)blockDim.x + threadIdx.x) >> 5);
    int lane = threadIdx.x & 31;
    if (warp >= N) return;

    int cnt = g_cnt[warp];
    int deg = cnt < CAP ? cnt : CAP;
    const int2* lst = g_edge + (size_t)warp * CAP;

    float4 acc = make_float4(0.f, 0.f, 0.f, 0.f);

    int e = 0;
    for (; e + 4 <= deg; e += 4) {
        int4 a = __ldg((const int4*)(lst + e));
        int4 b = __ldg((const int4*)(lst + e) + 1);
        float w0 = __int_as_float(a.y), w1 = __int_as_float(a.w);
        float w2 = __int_as_float(b.y), w3 = __int_as_float(b.w);
        float4 v0 = __ldg((const float4*)(H + (size_t)a.x * D) + lane);
        float4 v1 = __ldg((const float4*)(H + (size_t)a.z * D) + lane);
        float4 v2 = __ldg((const float4*)(H + (size_t)b.x * D) + lane);
        float4 v3 = __ldg((const float4*)(H + (size_t)b.z * D) + lane);
        acc.x += w0 * v0.x; acc.y += w0 * v0.y; acc.z += w0 * v0.z; acc.w += w0 * v0.w;
        acc.x += w1 * v1.x; acc.y += w1 * v1.y; acc.z += w1 * v1.z; acc.w += w1 * v1.w;
        acc.x += w2 * v2.x; acc.y += w2 * v2.y; acc.z += w2 * v2.z; acc.w += w2 * v2.w;
        acc.x += w3 * v3.x; acc.y += w3 * v3.y; acc.z += w3 * v3.z; acc.w += w3 * v3.w;
    }
    for (; e < deg; e++) {
        int2 p = __ldg(lst + e);
        float w = __int_as_float(p.y);
        float4 v = __ldg((const float4*)(H + (size_t)p.x * D) + lane);
        acc.x += w * v.x; acc.y += w * v.y; acc.z += w * v.z; acc.w += w * v.w;
    }

    float4* o = (float4*)(g_h + (size_t)warp * D) + lane;
    if (cnt > CAP) {
        float4 old = *o;
        acc.x += old.x; acc.y += old.y; acc.z += old.z; acc.w += old.w;
    }
    *o = acc;
}

// ---------------------------------------------------------------------------
// Kernel 4: fused BN -> Dense (TF32 tensor cores, 3-term split) -> exact GELU.
// Tile 128x128 per CTA, 512 threads / 16 warps, warp tile 32x32 (4x4 grid).
// K in 4 panels of 32.
// ---------------------------------------------------------------------------
__device__ __forceinline__ float gelu_exact(float x) {
    return 0.5f * x * (1.0f + erff(x * 0.70710678118654752f));
}

__device__ __forceinline__ float tf32_rna(float x) {
    unsigned int r;
    asm("cvt.rna.tf32.f32 %0, %1;" : "=r"(r) : "f"(x));
    return __uint_as_float(r);
}

#define LDA 40      // 32 + 8 pad (A panels: 128 rows x 32 k)
#define LDW 136     // 128 + 8 pad (W panels: 32 k x 128 c; also epilogue tile)
#define A_HI 0
#define A_LO (A_HI + BROWS * LDA)          // 5120
#define W_HI (A_LO + BROWS * LDA)          // 10240
#define W_LO (W_HI + 32 * LDW)             // 14592
#define SMEM_F (W_LO + 32 * LDW)           // 18944 floats = 75776 B

__global__ __launch_bounds__(512)
void gemm_kernel(const float* __restrict__ W,
                 const float* __restrict__ bias,
                 const float* __restrict__ gamma,
                 const float* __restrict__ beta,
                 const float* __restrict__ mean,
                 const float* __restrict__ var,
                 float* __restrict__ out,
                 int N) {
    extern __shared__ float sm[];
    __shared__ float sScale[D], sShift[D];

    int tid = threadIdx.x;
    if (tid < D) {
        float sc = gamma[tid] * rsqrtf(var[tid] + 1e-3f);
        sScale[tid] = sc;
        sShift[tid] = beta[tid] - mean[tid] * sc;
    }

    int row0 = blockIdx.x * BROWS;
    int wid  = tid >> 5;
    int m0   = (wid >> 2) * 32;     // warp row offset: 4 row-groups
    int n0   = (wid & 3) * 32;      // warp col offset: 4 col-groups

    wmma::fragment<wmma::accumulator, 16, 16, 8, float> acc[2][2];
    #pragma unroll
    for (int mf = 0; mf < 2; mf++)
        #pragma unroll
        for (int nf = 0; nf < 2; nf++) wmma::fill_fragment(acc[mf][nf], 0.0f);

    __syncthreads();   // sScale/sShift ready

    for (int p = 0; p < 4; p++) {
        int k0 = p * 32;

        // Stage A panel (BN applied, tf32 hi/lo split): 128 rows x 32 k.
        // 1024 float4 loads, 2 per thread.
        #pragma unroll
        for (int t = 0; t < 2; t++) {
            int i  = tid + t * 512;          // 0..1023
            int r  = i >> 3;                 // row 0..127
            int c4 = i & 7;                  // float4 within the 32-k panel
            int gr = row0 + r;
            float4 v = make_float4(0.f, 0.f, 0.f, 0.f);
            if (gr < N) v = __ldg((const float4*)(g_h + (size_t)gr * D) + (k0 >> 2) + c4);
            int c = k0 + c4 * 4;
            float x0 = v.x * sScale[c + 0] + sShift[c + 0];
            float x1 = v.y * sScale[c + 1] + sShift[c + 1];
            float x2 = v.z * sScale[c + 2] + sShift[c + 2];
            float x3 = v.w * sScale[c + 3] + sShift[c + 3];
            float h0 = tf32_rna(x0), h1 = tf32_rna(x1);
            float h2 = tf32_rna(x2), h3 = tf32_rna(x3);
            int o = r * LDA + c4 * 4;
            sm[A_HI + o + 0] = h0; sm[A_HI + o + 1] = h1;
            sm[A_HI + o + 2] = h2; sm[A_HI + o + 3] = h3;
            sm[A_LO + o + 0] = x0 - h0; sm[A_LO + o + 1] = x1 - h1;
            sm[A_LO + o + 2] = x2 - h2; sm[A_LO + o + 3] = x3 - h3;
        }

        // Stage W panel (tf32 hi/lo split): 32 k x 128 c. 1024 float4, 2/thread.
        #pragma unroll
        for (int t = 0; t < 2; t++) {
            int i  = tid + t * 512;          // 0..1023
            int k  = i >> 5;                 // 0..31
            int c4 = i & 31;                 // 32 float4 per 128-col row
            float4 v = __ldg((const float4*)(W + (size_t)(k0 + k) * D) + c4);
            float h0 = tf32_rna(v.x), h1 = tf32_rna(v.y);
            float h2 = tf32_rna(v.z), h3 = tf32_rna(v.w);
            int o = k * LDW + c4 * 4;
            sm[W_HI + o + 0] = h0; sm[W_HI + o + 1] = h1;
            sm[W_HI + o + 2] = h2; sm[W_HI + o + 3] = h3;
            sm[W_LO + o + 0] = v.x - h0; sm[W_LO + o + 1] = v.y - h1;
            sm[W_LO + o + 2] = v.z - h2; sm[W_LO + o + 3] = v.w - h3;
        }
        __syncthreads();

        #pragma unroll
        for (int kk = 0; kk < 4; kk++) {     // 4 k-steps of 8
            wmma::fragment<wmma::matrix_a, 16, 16, 8, wmma::precision::tf32, wmma::row_major> aHi[2], aLo[2];
            #pragma unroll
            for (int mf = 0; mf < 2; mf++) {
                wmma::load_matrix_sync(aHi[mf], sm + A_HI + (m0 + mf * 16) * LDA + kk * 8, LDA);
                wmma::load_matrix_sync(aLo[mf], sm + A_LO + (m0 + mf * 16) * LDA + kk * 8, LDA);
            }
            #pragma unroll
            for (int nf = 0; nf < 2; nf++) {
                wmma::fragment<wmma::matrix_b, 16, 16, 8, wmma::precision::tf32, wmma::row_major> bHi, bLo;
                wmma::load_matrix_sync(bHi, sm + W_HI + kk * 8 * LDW + n0 + nf * 16, LDW);
                wmma::load_matrix_sync(bLo, sm + W_LO + kk * 8 * LDW + n0 + nf * 16, LDW);
                #pragma unroll
                for (int mf = 0; mf < 2; mf++) {
                    wmma::mma_sync(acc[mf][nf], aHi[mf], bHi, acc[mf][nf]);
                    wmma::mma_sync(acc[mf][nf], aHi[mf], bLo, acc[mf][nf]);
                    wmma::mma_sync(acc[mf][nf], aLo[mf], bHi, acc[mf][nf]);
                }
            }
        }
        __syncthreads();
    }

    // Epilogue: dump accs to smem tile (128 x LDW), bias + exact GELU, store.
    #pragma unroll
    for (int mf = 0; mf < 2; mf++)
        #pragma unroll
        for (int nf = 0; nf < 2; nf++)
            wmma::store_matrix_sync(sm + (m0 + mf * 16) * LDW + n0 + nf * 16,
                                    acc[mf][nf], LDW, wmma::mem_row_major);
    __syncthreads();

    #pragma unroll
    for (int t = 0; t < 8; t++) {
        int i  = tid + t * 512;              // 0..4095  (128 rows x 32 float4)
        int r  = i >> 5;
        int c4 = i & 31;
        int gr = row0 + r;
        if (gr >= N) continue;
        int c = c4 * 4;
        const float* s = sm + r * LDW + c;
        float4 o;
        o.x = gelu_exact(s[0] + bias[c + 0]);
        o.y = gelu_exact(s[1] + bias[c + 1]);
        o.z = gelu_exact(s[2] + bias[c + 2]);
        o.w = gelu_exact(s[3] + bias[c + 3]);
        ((float4*)(out + (size_t)gr * D))[c4] = o;
    }
}

// ---------------------------------------------------------------------------
extern "C" void kernel_launch(void* const* d_in, const int* in_sizes, int n_in,
                              void* d_out, int out_size) {
    const float* H     = (const float*)d_in[0];
    const int*   src   = (const int*)  d_in[1];
    const int*   dst   = (const int*)  d_in[2];
    const float* ew    = (const float*)d_in[3];
    const float* gamma = (const float*)d_in[4];
    const float* beta  = (const float*)d_in[5];
    const float* mean  = (const float*)d_in[6];
    const float* var   = (const float*)d_in[7];
    const float* W     = (const float*)d_in[8];
    const float* bias  = (const float*)d_in[9];

    int N = in_sizes[0] / D;
    int E = in_sizes[1];

    zero_kernel<<<(N + 255) / 256, 256>>>(N);

    scatter_kernel<<<(E + 255) / 256, 256>>>(H, src, dst, ew, E);

    gather_kernel<<<(N * 32 + 255) / 256, 256>>>(H, N);

    int smem_bytes = SMEM_F * sizeof(float);   // ~74 KB
    cudaFuncSetAttribute(gemm_kernel,
                         cudaFuncAttributeMaxDynamicSharedMemorySize, smem_bytes);
    gemm_kernel<<<(N + BROWS - 1) / BROWS, 512, smem_bytes>>>(
        W, bias, gamma, beta, mean, var, (float*)d_out, N);
}

// round 7
// speedup vs baseline: 1.5093x; 1.5093x over previous
#include <cuda_runtime.h>
#include <cuda_bf16.h>
#include <mma.h>
#include <math.h>
#include <cstdint>

using namespace nvcuda;

#define D 128
#define MAX_N 100096
#define CAP 96
#define BROWS 128
#define PK 64                   // K panel size

// Scratch (allocation-free rule: __device__ globals).
__device__ float g_h[(size_t)MAX_N * D];          // SpMM accumulator
__device__ int   g_cnt[MAX_N];                    // per-node edge count
__device__ int2  g_edge[(size_t)MAX_N * CAP];     // edge buckets (src, w-bits)

// ---------------------------------------------------------------------------
__global__ void zero_kernel(int n) {
    int i = blockIdx.x * blockDim.x + threadIdx.x;
    if (i < n) g_cnt[i] = 0;
}

// ---------------------------------------------------------------------------
__global__ void scatter_kernel(const float* __restrict__ H,
                               const int*   __restrict__ src,
                               const int*   __restrict__ dst,
                               const float* __restrict__ ew,
                               int E) {
    int i = blockIdx.x * blockDim.x + threadIdx.x;
    if (i >= E) return;
    int d = dst[i];
    int pos = atomicAdd(&g_cnt[d], 1);
    int s = src[i];
    float w = ew[i];
    if (pos < CAP) {
        g_edge[(size_t)d * CAP + pos] = make_int2(s, __float_as_int(w));
    } else {
        // Statistically unreachable overflow; gather merges via cnt>CAP path.
        const float4* hp = (const float4*)(H + (size_t)s * D);
        float* o = g_h + (size_t)d * D;
        #pragma unroll 4
        for (int c = 0; c < D / 4; c++) {
            float4 v = __ldg(hp + c);
            asm volatile("red.global.add.v4.f32 [%0], {%1, %2, %3, %4};"
                         :: "l"(o + c * 4),
                            "f"(v.x * w), "f"(v.y * w), "f"(v.z * w), "f"(v.w * w)
                         : "memory");
        }
    }
}

// ---------------------------------------------------------------------------
__global__ __launch_bounds__(256)
void gather_kernel(const float* __restrict__ H, int N) {
    int warp = (int)((blockIdx.x * (unsigned)blockDim.x + threadIdx.x) >> 5);
    int lane = threadIdx.x & 31;
    if (warp >= N) return;

    int cnt = g_cnt[warp];
    int deg = cnt < CAP ? cnt : CAP;
    const int2* lst = g_edge + (size_t)warp * CAP;

    float4 acc = make_float4(0.f, 0.f, 0.f, 0.f);

    int e = 0;
    for (; e + 4 <= deg; e += 4) {
        int4 a = __ldg((const int4*)(lst + e));
        int4 b = __ldg((const int4*)(lst + e) + 1);
        float w0 = __int_as_float(a.y), w1 = __int_as_float(a.w);
        float w2 = __int_as_float(b.y), w3 = __int_as_float(b.w);
        float4 v0 = __ldg((const float4*)(H + (size_t)a.x * D) + lane);
        float4 v1 = __ldg((const float4*)(H + (size_t)a.z * D) + lane);
        float4 v2 = __ldg((const float4*)(H + (size_t)b.x * D) + lane);
        float4 v3 = __ldg((const float4*)(H + (size_t)b.z * D) + lane);
        acc.x += w0 * v0.x; acc.y += w0 * v0.y; acc.z += w0 * v0.z; acc.w += w0 * v0.w;
        acc.x += w1 * v1.x; acc.y += w1 * v1.y; acc.z += w1 * v1.z; acc.w += w1 * v1.w;
        acc.x += w2 * v2.x; acc.y += w2 * v2.y; acc.z += w2 * v2.z; acc.w += w2 * v2.w;
        acc.x += w3 * v3.x; acc.y += w3 * v3.y; acc.z += w3 * v3.z; acc.w += w3 * v3.w;
    }
    for (; e < deg; e++) {
        int2 p = __ldg(lst + e);
        float w = __int_as_float(p.y);
        float4 v = __ldg((const float4*)(H + (size_t)p.x * D) + lane);
        acc.x += w * v.x; acc.y += w * v.y; acc.z += w * v.z; acc.w += w * v.w;
    }

    float4* o = (float4*)(g_h + (size_t)warp * D) + lane;
    if (cnt > CAP) {
        float4 old = *o;
        acc.x += old.x; acc.y += old.y; acc.z += old.z; acc.w += old.w;
    }
    *o = acc;
}

// ---------------------------------------------------------------------------
// Kernel 4: fused BN -> Dense (bf16x3 tensor-core split) -> exact GELU.
// 128x128 tile/CTA, 256 threads / 8 warps (warp = 32m x 64n), K in 2 panels
// of 64.  D = Ahi*Bhi + Ahi*Blo + Alo*Bhi, fp32 accumulate; dropped lo*lo
// term is ~2^-18 relative.
// ---------------------------------------------------------------------------
__device__ __forceinline__ float gelu_exact(float x) {
    return 0.5f * x * (1.0f + erff(x * 0.70710678118654752f));
}

#define LDA2 72     // bf16 elems per A panel row  (64 + 8 pad)
#define LDW2 136    // bf16 elems per W panel row  (128 + 8 pad)
#define LDWF 136    // fp32 epilogue tile leading dim

// bf16-element offsets within the dynamic smem pool
#define A_HI 0
#define A_LO (A_HI + BROWS * LDA2)        // 9216
#define W_HI (A_LO + BROWS * LDA2)        // 18432
#define W_LO (W_HI + PK * LDW2)           // 27136
#define SMEM_BF (W_LO + PK * LDW2)        // 35840 bf16 = 71680 B
// epilogue reuses pool as fp32: 128*136*4 = 69632 B <= 71680 B

__global__ __launch_bounds__(256, 2)
void gemm_kernel(const float* __restrict__ W,
                 const float* __restrict__ bias,
                 const float* __restrict__ gamma,
                 const float* __restrict__ beta,
                 const float* __restrict__ mean,
                 const float* __restrict__ var,
                 float* __restrict__ out,
                 int N) {
    extern __shared__ float smf[];
    __nv_bfloat16* smb = (__nv_bfloat16*)smf;
    __shared__ float sScale[D], sShift[D];

    int tid = threadIdx.x;
    if (tid < D) {
        float sc = gamma[tid] * rsqrtf(var[tid] + 1e-3f);
        sScale[tid] = sc;
        sShift[tid] = beta[tid] - mean[tid] * sc;
    }

    int row0 = blockIdx.x * BROWS;
    int wid  = tid >> 5;
    int m0   = (wid >> 1) * 32;     // 4 m-groups of 32
    int n0   = (wid & 1) * 64;      // 2 n-groups of 64

    wmma::fragment<wmma::accumulator, 16, 16, 16, float> acc[2][4];
    #pragma unroll
    for (int mf = 0; mf < 2; mf++)
        #pragma unroll
        for (int nf = 0; nf < 4; nf++) wmma::fill_fragment(acc[mf][nf], 0.0f);

    __syncthreads();   // sScale/sShift ready

    for (int p = 0; p < 2; p++) {
        int k0 = p * PK;

        // Stage A panel (BN + bf16 hi/lo split): 128 rows x 64 k.
        // 2048 float4 loads, 8 per thread.
        #pragma unroll
        for (int t = 0; t < 8; t++) {
            int i  = tid + t * 256;          // 0..2047
            int r  = i >> 4;                 // row 0..127  (16 float4/row)
            int c4 = i & 15;
            int gr = row0 + r;
            float4 v = make_float4(0.f, 0.f, 0.f, 0.f);
            if (gr < N) v = __ldg((const float4*)(g_h + (size_t)gr * D) + (k0 >> 2) + c4);
            int c = k0 + c4 * 4;
            float x0 = v.x * sScale[c + 0] + sShift[c + 0];
            float x1 = v.y * sScale[c + 1] + sShift[c + 1];
            float x2 = v.z * sScale[c + 2] + sShift[c + 2];
            float x3 = v.w * sScale[c + 3] + sShift[c + 3];
            __nv_bfloat16 h0 = __float2bfloat16_rn(x0);
            __nv_bfloat16 h1 = __float2bfloat16_rn(x1);
            __nv_bfloat16 h2 = __float2bfloat16_rn(x2);
            __nv_bfloat16 h3 = __float2bfloat16_rn(x3);
            __nv_bfloat16 l0 = __float2bfloat16_rn(x0 - __bfloat162float(h0));
            __nv_bfloat16 l1 = __float2bfloat16_rn(x1 - __bfloat162float(h1));
            __nv_bfloat16 l2 = __float2bfloat16_rn(x2 - __bfloat162float(h2));
            __nv_bfloat16 l3 = __float2bfloat16_rn(x3 - __bfloat162float(h3));
            int o = r * LDA2 + c4 * 4;       // even -> bfloat162 aligned
            *(__nv_bfloat162*)(smb + A_HI + o)     = __halves2bfloat162(h0, h1);
            *(__nv_bfloat162*)(smb + A_HI + o + 2) = __halves2bfloat162(h2, h3);
            *(__nv_bfloat162*)(smb + A_LO + o)     = __halves2bfloat162(l0, l1);
            *(__nv_bfloat162*)(smb + A_LO + o + 2) = __halves2bfloat162(l2, l3);
        }

        // Stage W panel (bf16 hi/lo split): 64 k x 128 c.  2048 float4.
        #pragma unroll
        for (int t = 0; t < 8; t++) {
            int i  = tid + t * 256;          // 0..2047
            int k  = i >> 5;                 // 0..63  (32 float4/row)
            int c4 = i & 31;
            float4 v = __ldg((const float4*)(W + (size_t)(k0 + k) * D) + c4);
            __nv_bfloat16 h0 = __float2bfloat16_rn(v.x);
            __nv_bfloat16 h1 = __float2bfloat16_rn(v.y);
            __nv_bfloat16 h2 = __float2bfloat16_rn(v.z);
            __nv_bfloat16 h3 = __float2bfloat16_rn(v.w);
            __nv_bfloat16 l0 = __float2bfloat16_rn(v.x - __bfloat162float(h0));
            __nv_bfloat16 l1 = __float2bfloat16_rn(v.y - __bfloat162float(h1));
            __nv_bfloat16 l2 = __float2bfloat16_rn(v.z - __bfloat162float(h2));
            __nv_bfloat16 l3 = __float2bfloat16_rn(v.w - __bfloat162float(h3));
            int o = k * LDW2 + c4 * 4;
            *(__nv_bfloat162*)(smb + W_HI + o)     = __halves2bfloat162(h0, h1);
            *(__nv_bfloat162*)(smb + W_HI + o + 2) = __halves2bfloat162(h2, h3);
            *(__nv_bfloat162*)(smb + W_LO + o)     = __halves2bfloat162(l0, l1);
            *(__nv_bfloat162*)(smb + W_LO + o + 2) = __halves2bfloat162(l2, l3);
        }
        __syncthreads();

        #pragma unroll
        for (int kk = 0; kk < PK / 16; kk++) {   // 4 k-steps of 16
            wmma::fragment<wmma::matrix_a, 16, 16, 16, __nv_bfloat16, wmma::row_major> aHi[2], aLo[2];
            #pragma unroll
            for (int mf = 0; mf < 2; mf++) {
                const __nv_bfloat16* ah = smb + A_HI + (m0 + mf * 16) * LDA2 + kk * 16;
                const __nv_bfloat16* al = smb + A_LO + (m0 + mf * 16) * LDA2 + kk * 16;
                wmma::load_matrix_sync(aHi[mf], ah, LDA2);
                wmma::load_matrix_sync(aLo[mf], al, LDA2);
            }
            #pragma unroll
            for (int nf = 0; nf < 4; nf++) {
                wmma::fragment<wmma::matrix_b, 16, 16, 16, __nv_bfloat16, wmma::row_major> bHi, bLo;
                wmma::load_matrix_sync(bHi, smb + W_HI + kk * 16 * LDW2 + n0 + nf * 16, LDW2);
                wmma::load_matrix_sync(bLo, smb + W_LO + kk * 16 * LDW2 + n0 + nf * 16, LDW2);
                #pragma unroll
                for (int mf = 0; mf < 2; mf++) {
                    wmma::mma_sync(acc[mf][nf], aHi[mf], bHi, acc[mf][nf]);
                    wmma::mma_sync(acc[mf][nf], aHi[mf], bLo, acc[mf][nf]);
                    wmma::mma_sync(acc[mf][nf], aLo[mf], bHi, acc[mf][nf]);
                }
            }
        }
        __syncthreads();
    }

    // Epilogue: dump accs to fp32 smem tile, bias + exact GELU, store.
    #pragma unroll
    for (int mf = 0; mf < 2; mf++)
        #pragma unroll
        for (int nf = 0; nf < 4; nf++)
            wmma::store_matrix_sync(smf + (m0 + mf * 16) * LDWF + n0 + nf * 16,
                                    acc[mf][nf], LDWF, wmma::mem_row_major);
    __syncthreads();

    #pragma unroll
    for (int t = 0; t < 16; t++) {
        int i  = tid + t * 256;              // 0..4095  (128 rows x 32 float4)
        int r  = i >> 5;
        int c4 = i & 31;
        int gr = row0 + r;
        if (gr >= N) continue;
        int c = c4 * 4;
        const float* s = smf + r * LDWF + c;
        float4 o;
        o.x = gelu_exact(s[0] + bias[c + 0]);
        o.y = gelu_exact(s[1] + bias[c + 1]);
        o.z = gelu_exact(s[2] + bias[c + 2]);
        o.w = gelu_exact(s[3] + bias[c + 3]);
        ((float4*)(out + (size_t)gr * D))[c4] = o;
    }
}

// ---------------------------------------------------------------------------
extern "C" void kernel_launch(void* const* d_in, const int* in_sizes, int n_in,
                              void* d_out, int out_size) {
    const float* H     = (const float*)d_in[0];
    const int*   src   = (const int*)  d_in[1];
    const int*   dst   = (const int*)  d_in[2];
    const float* ew    = (const float*)d_in[3];
    const float* gamma = (const float*)d_in[4];
    const float* beta  = (const float*)d_in[5];
    const float* mean  = (const float*)d_in[6];
    const float* var   = (const float*)d_in[7];
    const float* W     = (const float*)d_in[8];
    const float* bias  = (const float*)d_in[9];

    int N = in_sizes[0] / D;
    int E = in_sizes[1];

    zero_kernel<<<(N + 255) / 256, 256>>>(N);

    scatter_kernel<<<(E + 255) / 256, 256>>>(H, src, dst, ew, E);

    gather_kernel<<<(N * 32 + 255) / 256, 256>>>(H, N);

    int smem_bytes = SMEM_BF * 2;            // 71680 B
    cudaFuncSetAttribute(gemm_kernel,
                         cudaFuncAttributeMaxDynamicSharedMemorySize, smem_bytes);
    gemm_kernel<<<(N + BROWS - 1) / BROWS, 256, smem_bytes>>>(
        W, bias, gamma, beta, mean, var, (float*)d_out, N);
}

// round 8
// speedup vs baseline: 1.5358x; 1.0176x over previous
#include <cuda_runtime.h>
#include <cuda_bf16.h>
#include <mma.h>
#include <math.h>
#include <cstdint>

using namespace nvcuda;

#define D 128
#define MAX_N 100096
#define CAP 96
#define BROWS 128
#define PK 64                   // K panel size

// Scratch (allocation-free rule: __device__ globals).
__device__ float          g_h[(size_t)MAX_N * D];    // fp32 accumulator (overflow path only)
__device__ __nv_bfloat16  g_hi[(size_t)MAX_N * D];   // BN(h) bf16 high part
__device__ __nv_bfloat16  g_lo[(size_t)MAX_N * D];   // BN(h) bf16 low part
__device__ int            g_cnt[MAX_N];              // per-node edge count
__device__ int2           g_edge[(size_t)MAX_N * CAP]; // edge buckets (src, w-bits)

// ---------------------------------------------------------------------------
__global__ void zero_kernel(int n) {
    int i = blockIdx.x * blockDim.x + threadIdx.x;
    if (i < n) g_cnt[i] = 0;
}

// ---------------------------------------------------------------------------
__global__ void scatter_kernel(const float* __restrict__ H,
                               const int*   __restrict__ src,
                               const int*   __restrict__ dst,
                               const float* __restrict__ ew,
                               int E) {
    int i = blockIdx.x * blockDim.x + threadIdx.x;
    if (i >= E) return;
    int d = dst[i];
    int pos = atomicAdd(&g_cnt[d], 1);
    int s = src[i];
    float w = ew[i];
    if (pos < CAP) {
        g_edge[(size_t)d * CAP + pos] = make_int2(s, __float_as_int(w));
    } else {
        // Statistically unreachable (11 sigma); gather merges via cnt>CAP path.
        const float4* hp = (const float4*)(H + (size_t)s * D);
        float* o = g_h + (size_t)d * D;
        #pragma unroll 4
        for (int c = 0; c < D / 4; c++) {
            float4 v = __ldg(hp + c);
            asm volatile("red.global.add.v4.f32 [%0], {%1, %2, %3, %4};"
                         :: "l"(o + c * 4),
                            "f"(v.x * w), "f"(v.y * w), "f"(v.z * w), "f"(v.w * w)
                         : "memory");
        }
    }
}

// ---------------------------------------------------------------------------
// Gather: one warp per node; lane owns 4 columns.  Epilogue applies BN and
// emits bf16 hi/lo split directly (feeds the tensor-core GEMM unconverted).
// ---------------------------------------------------------------------------
__global__ __launch_bounds__(256)
void gather_kernel(const float* __restrict__ H,
                   const float* __restrict__ gamma,
                   const float* __restrict__ beta,
                   const float* __restrict__ mean,
                   const float* __restrict__ var,
                   int N) {
    int warp = (int)((blockIdx.x * (unsigned)blockDim.x + threadIdx.x) >> 5);
    int lane = threadIdx.x & 31;
    if (warp >= N) return;

    int cnt = g_cnt[warp];
    int deg = cnt < CAP ? cnt : CAP;
    const int2* lst = g_edge + (size_t)warp * CAP;

    float4 acc = make_float4(0.f, 0.f, 0.f, 0.f);

    int e = 0;
    for (; e + 4 <= deg; e += 4) {
        int4 a = __ldg((const int4*)(lst + e));
        int4 b = __ldg((const int4*)(lst + e) + 1);
        float w0 = __int_as_float(a.y), w1 = __int_as_float(a.w);
        float w2 = __int_as_float(b.y), w3 = __int_as_float(b.w);
        float4 v0 = __ldg((const float4*)(H + (size_t)a.x * D) + lane);
        float4 v1 = __ldg((const float4*)(H + (size_t)a.z * D) + lane);
        float4 v2 = __ldg((const float4*)(H + (size_t)b.x * D) + lane);
        float4 v3 = __ldg((const float4*)(H + (size_t)b.z * D) + lane);
        acc.x += w0 * v0.x; acc.y += w0 * v0.y; acc.z += w0 * v0.z; acc.w += w0 * v0.w;
        acc.x += w1 * v1.x; acc.y += w1 * v1.y; acc.z += w1 * v1.z; acc.w += w1 * v1.w;
        acc.x += w2 * v2.x; acc.y += w2 * v2.y; acc.z += w2 * v2.z; acc.w += w2 * v2.w;
        acc.x += w3 * v3.x; acc.y += w3 * v3.y; acc.z += w3 * v3.z; acc.w += w3 * v3.w;
    }
    for (; e < deg; e++) {
        int2 p = __ldg(lst + e);
        float w = __int_as_float(p.y);
        float4 v = __ldg((const float4*)(H + (size_t)p.x * D) + lane);
        acc.x += w * v.x; acc.y += w * v.y; acc.z += w * v.z; acc.w += w * v.w;
    }

    if (cnt > CAP) {   // merge rare overflow contributions
        float4 old = *((const float4*)(g_h + (size_t)warp * D) + lane);
        acc.x += old.x; acc.y += old.y; acc.z += old.z; acc.w += old.w;
    }

    // BN (inference) for this lane's 4 columns.
    float4 g4 = __ldg((const float4*)gamma + lane);
    float4 b4 = __ldg((const float4*)beta  + lane);
    float4 m4 = __ldg((const float4*)mean  + lane);
    float4 v4 = __ldg((const float4*)var   + lane);
    float s0 = g4.x * rsqrtf(v4.x + 1e-3f);
    float s1 = g4.y * rsqrtf(v4.y + 1e-3f);
    float s2 = g4.z * rsqrtf(v4.z + 1e-3f);
    float s3 = g4.w * rsqrtf(v4.w + 1e-3f);
    float x0 = acc.x * s0 + (b4.x - m4.x * s0);
    float x1 = acc.y * s1 + (b4.y - m4.y * s1);
    float x2 = acc.z * s2 + (b4.z - m4.z * s2);
    float x3 = acc.w * s3 + (b4.w - m4.w * s3);

    __nv_bfloat16 h0 = __float2bfloat16_rn(x0);
    __nv_bfloat16 h1 = __float2bfloat16_rn(x1);
    __nv_bfloat16 h2 = __float2bfloat16_rn(x2);
    __nv_bfloat16 h3 = __float2bfloat16_rn(x3);
    __nv_bfloat16 l0 = __float2bfloat16_rn(x0 - __bfloat162float(h0));
    __nv_bfloat16 l1 = __float2bfloat16_rn(x1 - __bfloat162float(h1));
    __nv_bfloat16 l2 = __float2bfloat16_rn(x2 - __bfloat162float(h2));
    __nv_bfloat16 l3 = __float2bfloat16_rn(x3 - __bfloat162float(h3));

    size_t base = (size_t)warp * D + lane * 4;
    *(__nv_bfloat162*)(g_hi + base)     = __halves2bfloat162(h0, h1);
    *(__nv_bfloat162*)(g_hi + base + 2) = __halves2bfloat162(h2, h3);
    *(__nv_bfloat162*)(g_lo + base)     = __halves2bfloat162(l0, l1);
    *(__nv_bfloat162*)(g_lo + base + 2) = __halves2bfloat162(l2, l3);
}

// ---------------------------------------------------------------------------
// Kernel 4: Dense (bf16x3 tensor-core split) -> bias -> exact GELU.
// A panels arrive pre-split from gather: staging is straight uint4 copies.
// 128x128 tile/CTA, 256 threads / 8 warps (warp = 32m x 64n), K in 2 panels.
// ---------------------------------------------------------------------------
__device__ __forceinline__ float gelu_exact(float x) {
    return 0.5f * x * (1.0f + erff(x * 0.70710678118654752f));
}

#define LDA2 72     // bf16 elems per A panel row  (64 + 8 pad)
#define LDW2 136    // bf16 elems per W panel row  (128 + 8 pad)
#define LDWF 136    // fp32 epilogue tile leading dim

#define A_HI 0
#define A_LO (A_HI + BROWS * LDA2)        // 9216
#define W_HI (A_LO + BROWS * LDA2)        // 18432
#define W_LO (W_HI + PK * LDW2)           // 27136
#define SMEM_BF (W_LO + PK * LDW2)        // 35840 bf16 = 71680 B
// epilogue reuses pool as fp32: 128*136*4 = 69632 B <= 71680 B

__global__ __launch_bounds__(256, 2)
void gemm_kernel(const float* __restrict__ W,
                 const float* __restrict__ bias,
                 float* __restrict__ out,
                 int N) {
    extern __shared__ float smf[];
    __nv_bfloat16* smb = (__nv_bfloat16*)smf;

    int tid  = threadIdx.x;
    int row0 = blockIdx.x * BROWS;
    int wid  = tid >> 5;
    int m0   = (wid >> 1) * 32;
    int n0   = (wid & 1) * 64;

    wmma::fragment<wmma::accumulator, 16, 16, 16, float> acc[2][4];
    #pragma unroll
    for (int mf = 0; mf < 2; mf++)
        #pragma unroll
        for (int nf = 0; nf < 4; nf++) wmma::fill_fragment(acc[mf][nf], 0.0f);

    for (int p = 0; p < 2; p++) {
        int k0 = p * PK;

        // Stage A panels: straight copies of pre-split bf16 (8 uint4/thread).
        #pragma unroll
        for (int t = 0; t < 4; t++) {
            int i  = tid + t * 256;          // 0..1023
            int r  = i >> 3;                 // row 0..127 (8 uint4 per row)
            int c8 = i & 7;                  // uint4 index (8 bf16 each)
            int gr = row0 + r;
            uint4 vh = make_uint4(0u, 0u, 0u, 0u);
            uint4 vl = make_uint4(0u, 0u, 0u, 0u);
            if (gr < N) {
                size_t off = (size_t)gr * D + k0;
                vh = __ldg((const uint4*)(g_hi + off) + c8);
                vl = __ldg((const uint4*)(g_lo + off) + c8);
            }
            int o = r * LDA2 + c8 * 8;
            *(uint4*)(smb + A_HI + o) = vh;
            *(uint4*)(smb + A_LO + o) = vl;
        }

        // Stage W panel (bf16 hi/lo split): 64 k x 128 c.  2048 float4.
        #pragma unroll
        for (int t = 0; t < 8; t++) {
            int i  = tid + t * 256;          // 0..2047
            int k  = i >> 5;                 // 0..63  (32 float4/row)
            int c4 = i & 31;
            float4 v = __ldg((const float4*)(W + (size_t)(k0 + k) * D) + c4);
            __nv_bfloat16 h0 = __float2bfloat16_rn(v.x);
            __nv_bfloat16 h1 = __float2bfloat16_rn(v.y);
            __nv_bfloat16 h2 = __float2bfloat16_rn(v.z);
            __nv_bfloat16 h3 = __float2bfloat16_rn(v.w);
            __nv_bfloat16 l0 = __float2bfloat16_rn(v.x - __bfloat162float(h0));
            __nv_bfloat16 l1 = __float2bfloat16_rn(v.y - __bfloat162float(h1));
            __nv_bfloat16 l2 = __float2bfloat16_rn(v.z - __bfloat162float(h2));
            __nv_bfloat16 l3 = __float2bfloat16_rn(v.w - __bfloat162float(h3));
            int o = k * LDW2 + c4 * 4;
            *(__nv_bfloat162*)(smb + W_HI + o)     = __halves2bfloat162(h0, h1);
            *(__nv_bfloat162*)(smb + W_HI + o + 2) = __halves2bfloat162(h2, h3);
            *(__nv_bfloat162*)(smb + W_LO + o)     = __halves2bfloat162(l0, l1);
            *(__nv_bfloat162*)(smb + W_LO + o + 2) = __halves2bfloat162(l2, l3);
        }
        __syncthreads();

        #pragma unroll
        for (int kk = 0; kk < PK / 16; kk++) {
            wmma::fragment<wmma::matrix_a, 16, 16, 16, __nv_bfloat16, wmma::row_major> aHi[2], aLo[2];
            #pragma unroll
            for (int mf = 0; mf < 2; mf++) {
                wmma::load_matrix_sync(aHi[mf], smb + A_HI + (m0 + mf * 16) * LDA2 + kk * 16, LDA2);
                wmma::load_matrix_sync(aLo[mf], smb + A_LO + (m0 + mf * 16) * LDA2 + kk * 16, LDA2);
            }
            #pragma unroll
            for (int nf = 0; nf < 4; nf++) {
                wmma::fragment<wmma::matrix_b, 16, 16, 16, __nv_bfloat16, wmma::row_major> bHi, bLo;
                wmma::load_matrix_sync(bHi, smb + W_HI + kk * 16 * LDW2 + n0 + nf * 16, LDW2);
                wmma::load_matrix_sync(bLo, smb + W_LO + kk * 16 * LDW2 + n0 + nf * 16, LDW2);
                #pragma unroll
                for (int mf = 0; mf < 2; mf++) {
                    wmma::mma_sync(acc[mf][nf], aHi[mf], bHi, acc[mf][nf]);
                    wmma::mma_sync(acc[mf][nf], aHi[mf], bLo, acc[mf][nf]);
                    wmma::mma_sync(acc[mf][nf], aLo[mf], bHi, acc[mf][nf]);
                }
            }
        }
        __syncthreads();
    }

    // Epilogue: dump accs to fp32 smem tile, bias + exact GELU, store.
    #pragma unroll
    for (int mf = 0; mf < 2; mf++)
        #pragma unroll
        for (int nf = 0; nf < 4; nf++)
            wmma::store_matrix_sync(smf + (m0 + mf * 16) * LDWF + n0 + nf * 16,
                                    acc[mf][nf], LDWF, wmma::mem_row_major);
    __syncthreads();

    #pragma unroll
    for (int t = 0; t < 16; t++) {
        int i  = tid + t * 256;              // 0..4095  (128 rows x 32 float4)
        int r  = i >> 5;
        int c4 = i & 31;
        int gr = row0 + r;
        if (gr >= N) continue;
        int c = c4 * 4;
        const float* s = smf + r * LDWF + c;
        float4 o;
        o.x = gelu_exact(s[0] + bias[c + 0]);
        o.y = gelu_exact(s[1] + bias[c + 1]);
        o.z = gelu_exact(s[2] + bias[c + 2]);
        o.w = gelu_exact(s[3] + bias[c + 3]);
        ((float4*)(out + (size_t)gr * D))[c4] = o;
    }
}

// ---------------------------------------------------------------------------
extern "C" void kernel_launch(void* const* d_in, const int* in_sizes, int n_in,
                              void* d_out, int out_size) {
    const float* H     = (const float*)d_in[0];
    const int*   src   = (const int*)  d_in[1];
    const int*   dst   = (const int*)  d_in[2];
    const float* ew    = (const float*)d_in[3];
    const float* gamma = (const float*)d_in[4];
    const float* beta  = (const float*)d_in[5];
    const float* mean  = (const float*)d_in[6];
    const float* var   = (const float*)d_in[7];
    const float* W     = (const float*)d_in[8];
    const float* bias  = (const float*)d_in[9];

    int N = in_sizes[0] / D;
    int E = in_sizes[1];

    zero_kernel<<<(N + 255) / 256, 256>>>(N);

    scatter_kernel<<<(E + 255) / 256, 256>>>(H, src, dst, ew, E);

    gather_kernel<<<(N * 32 + 255) / 256, 256>>>(H, gamma, beta, mean, var, N);

    int smem_bytes = SMEM_BF * 2;            // 71680 B
    cudaFuncSetAttribute(gemm_kernel,
                         cudaFuncAttributeMaxDynamicSharedMemorySize, smem_bytes);
    gemm_kernel<<<(N + BROWS - 1) / BROWS, 256, smem_bytes>>>(
        W, bias, (float*)d_out, N);
}

// round 9
// speedup vs baseline: 1.6563x; 1.0784x over previous
#include <cuda_runtime.h>
#include <cuda_bf16.h>
#include <cuda_fp16.h>
#include <mma.h>
#include <math.h>
#include <cstdint>

using namespace nvcuda;

#define D 128
#define MAX_N 100096
#define CAP 96
#define BROWS 128
#define PK 64                   // K panel size

// Scratch (allocation-free rule: __device__ globals).
__device__ float   g_h[(size_t)MAX_N * D];      // fp32 accumulator (overflow path only)
__device__ __half  g_Y[(size_t)MAX_N * D];      // Y = H * W' in fp16
__device__ float   g_c[D];                      // c = t.W + b
__device__ int     g_cnt[MAX_N];                // per-node edge count
__device__ int2    g_edge[(size_t)MAX_N * CAP]; // edge buckets (src, w-bits)

// ---------------------------------------------------------------------------
__global__ void zero_kernel(int n) {
    int i = blockIdx.x * blockDim.x + threadIdx.x;
    if (i < n) g_cnt[i] = 0;
}

// c[j] = bias[j] + sum_k (beta_k - mean_k*s_k) * W[k][j],  s_k = gamma_k/sqrt(var_k+eps)
__global__ void prep_c_kernel(const float* __restrict__ W,
                              const float* __restrict__ bias,
                              const float* __restrict__ gamma,
                              const float* __restrict__ beta,
                              const float* __restrict__ mean,
                              const float* __restrict__ var) {
    int j = threadIdx.x;
    float acc = bias[j];
    for (int k = 0; k < D; k++) {
        float s = gamma[k] * rsqrtf(var[k] + 1e-3f);
        float t = beta[k] - mean[k] * s;
        acc += t * W[k * D + j];
    }
    g_c[j] = acc;
}

// ---------------------------------------------------------------------------
// Scatter: bucket edges by destination.  Overflow (11-sigma unreachable)
// accumulates w*Y[src] directly into g_h (Y-space); gather merges it.
// ---------------------------------------------------------------------------
__global__ void scatter_kernel(const int*   __restrict__ src,
                               const int*   __restrict__ dst,
                               const float* __restrict__ ew,
                               int E) {
    int i = blockIdx.x * blockDim.x + threadIdx.x;
    if (i >= E) return;
    int d = dst[i];
    int pos = atomicAdd(&g_cnt[d], 1);
    int s = src[i];
    float w = ew[i];
    if (pos < CAP) {
        g_edge[(size_t)d * CAP + pos] = make_int2(s, __float_as_int(w));
    } else {
        const __half* yp = g_Y + (size_t)s * D;
        float* o = g_h + (size_t)d * D;
        for (int c = 0; c < D; c += 4) {
            float v0 = __half2float(yp[c + 0]) * w;
            float v1 = __half2float(yp[c + 1]) * w;
            float v2 = __half2float(yp[c + 2]) * w;
            float v3 = __half2float(yp[c + 3]) * w;
            asm volatile("red.global.add.v4.f32 [%0], {%1, %2, %3, %4};"
                         :: "l"(o + c), "f"(v0), "f"(v1), "f"(v2), "f"(v3)
                         : "memory");
        }
    }
}

// ---------------------------------------------------------------------------
// GEMM: Y = H * W'   (bf16x3 tensor-core split), Y stored fp16.
// 128x128 tile/CTA, 256 threads / 8 warps (warp = 32m x 64n), K in 2 panels.
// W' = diag(s) * W applied during W staging.
// ---------------------------------------------------------------------------
#define LDA2 72     // bf16 elems per A panel row  (64 + 8 pad)
#define LDW2 136    // bf16 elems per W panel row  (128 + 8 pad)
#define LDWF 136    // fp32 epilogue tile leading dim

#define A_HI 0
#define A_LO (A_HI + BROWS * LDA2)        // 9216
#define W_HI (A_LO + BROWS * LDA2)        // 18432
#define W_LO (W_HI + PK * LDW2)           // 27136
#define SMEM_BF (W_LO + PK * LDW2)        // 35840 bf16 = 71680 B
// epilogue reuses pool as fp32: 128*136*4 = 69632 B <= 71680 B

__global__ __launch_bounds__(256, 2)
void gemm_kernel(const float* __restrict__ H,
                 const float* __restrict__ W,
                 const float* __restrict__ gamma,
                 const float* __restrict__ var,
                 int N) {
    extern __shared__ float smf[];
    __nv_bfloat16* smb = (__nv_bfloat16*)smf;
    __shared__ float sS[D];

    int tid  = threadIdx.x;
    if (tid < D) sS[tid] = gamma[tid] * rsqrtf(var[tid] + 1e-3f);

    int row0 = blockIdx.x * BROWS;
    int wid  = tid >> 5;
    int m0   = (wid >> 1) * 32;
    int n0   = (wid & 1) * 64;

    wmma::fragment<wmma::accumulator, 16, 16, 16, float> acc[2][4];
    #pragma unroll
    for (int mf = 0; mf < 2; mf++)
        #pragma unroll
        for (int nf = 0; nf < 4; nf++) wmma::fill_fragment(acc[mf][nf], 0.0f);

    __syncthreads();   // sS ready

    for (int p = 0; p < 2; p++) {
        int k0 = p * PK;

        // Stage A panel (bf16 hi/lo split of H): 128 rows x 64 k.
        #pragma unroll
        for (int t = 0; t < 8; t++) {
            int i  = tid + t * 256;          // 0..2047
            int r  = i >> 4;                 // row 0..127  (16 float4/row)
            int c4 = i & 15;
            int gr = row0 + r;
            float4 v = make_float4(0.f, 0.f, 0.f, 0.f);
            if (gr < N) v = __ldg((const float4*)(H + (size_t)gr * D) + (k0 >> 2) + c4);
            __nv_bfloat16 h0 = __float2bfloat16_rn(v.x);
            __nv_bfloat16 h1 = __float2bfloat16_rn(v.y);
            __nv_bfloat16 h2 = __float2bfloat16_rn(v.z);
            __nv_bfloat16 h3 = __float2bfloat16_rn(v.w);
            __nv_bfloat16 l0 = __float2bfloat16_rn(v.x - __bfloat162float(h0));
            __nv_bfloat16 l1 = __float2bfloat16_rn(v.y - __bfloat162float(h1));
            __nv_bfloat16 l2 = __float2bfloat16_rn(v.z - __bfloat162float(h2));
            __nv_bfloat16 l3 = __float2bfloat16_rn(v.w - __bfloat162float(h3));
            int o = r * LDA2 + c4 * 4;
            *(__nv_bfloat162*)(smb + A_HI + o)     = __halves2bfloat162(h0, h1);
            *(__nv_bfloat162*)(smb + A_HI + o + 2) = __halves2bfloat162(h2, h3);
            *(__nv_bfloat162*)(smb + A_LO + o)     = __halves2bfloat162(l0, l1);
            *(__nv_bfloat162*)(smb + A_LO + o + 2) = __halves2bfloat162(l2, l3);
        }

        // Stage W' panel (scaled by s_k, bf16 hi/lo split): 64 k x 128 c.
        #pragma unroll
        for (int t = 0; t < 8; t++) {
            int i  = tid + t * 256;          // 0..2047
            int k  = i >> 5;                 // 0..63  (32 float4/row)
            int c4 = i & 31;
            float sk = sS[k0 + k];
            float4 v = __ldg((const float4*)(W + (size_t)(k0 + k) * D) + c4);
            v.x *= sk; v.y *= sk; v.z *= sk; v.w *= sk;
            __nv_bfloat16 h0 = __float2bfloat16_rn(v.x);
            __nv_bfloat16 h1 = __float2bfloat16_rn(v.y);
            __nv_bfloat16 h2 = __float2bfloat16_rn(v.z);
            __nv_bfloat16 h3 = __float2bfloat16_rn(v.w);
            __nv_bfloat16 l0 = __float2bfloat16_rn(v.x - __bfloat162float(h0));
            __nv_bfloat16 l1 = __float2bfloat16_rn(v.y - __bfloat162float(h1));
            __nv_bfloat16 l2 = __float2bfloat16_rn(v.z - __bfloat162float(h2));
            __nv_bfloat16 l3 = __float2bfloat16_rn(v.w - __bfloat162float(h3));
            int o = k * LDW2 + c4 * 4;
            *(__nv_bfloat162*)(smb + W_HI + o)     = __halves2bfloat162(h0, h1);
            *(__nv_bfloat162*)(smb + W_HI + o + 2) = __halves2bfloat162(h2, h3);
            *(__nv_bfloat162*)(smb + W_LO + o)     = __halves2bfloat162(l0, l1);
            *(__nv_bfloat162*)(smb + W_LO + o + 2) = __halves2bfloat162(l2, l3);
        }
        __syncthreads();

        #pragma unroll
        for (int kk = 0; kk < PK / 16; kk++) {
            wmma::fragment<wmma::matrix_a, 16, 16, 16, __nv_bfloat16, wmma::row_major> aHi[2], aLo[2];
            #pragma unroll
            for (int mf = 0; mf < 2; mf++) {
                wmma::load_matrix_sync(aHi[mf], smb + A_HI + (m0 + mf * 16) * LDA2 + kk * 16, LDA2);
                wmma::load_matrix_sync(aLo[mf], smb + A_LO + (m0 + mf * 16) * LDA2 + kk * 16, LDA2);
            }
            #pragma unroll
            for (int nf = 0; nf < 4; nf++) {
                wmma::fragment<wmma::matrix_b, 16, 16, 16, __nv_bfloat16, wmma::row_major> bHi, bLo;
                wmma::load_matrix_sync(bHi, smb + W_HI + kk * 16 * LDW2 + n0 + nf * 16, LDW2);
                wmma::load_matrix_sync(bLo, smb + W_LO + kk * 16 * LDW2 + n0 + nf * 16, LDW2);
                #pragma unroll
                for (int mf = 0; mf < 2; mf++) {
                    wmma::mma_sync(acc[mf][nf], aHi[mf], bHi, acc[mf][nf]);
                    wmma::mma_sync(acc[mf][nf], aHi[mf], bLo, acc[mf][nf]);
                    wmma::mma_sync(acc[mf][nf], aLo[mf], bHi, acc[mf][nf]);
                }
            }
        }
        __syncthreads();
    }

    // Epilogue: dump accs to fp32 smem tile, convert to fp16 Y, store.
    #pragma unroll
    for (int mf = 0; mf < 2; mf++)
        #pragma unroll
        for (int nf = 0; nf < 4; nf++)
            wmma::store_matrix_sync(smf + (m0 + mf * 16) * LDWF + n0 + nf * 16,
                                    acc[mf][nf], LDWF, wmma::mem_row_major);
    __syncthreads();

    #pragma unroll
    for (int t = 0; t < 16; t++) {
        int i  = tid + t * 256;              // 0..4095  (128 rows x 32 groups of 4)
        int r  = i >> 5;
        int c4 = i & 31;
        int gr = row0 + r;
        if (gr >= N) continue;
        const float* s = smf + r * LDWF + c4 * 4;
        __half2 p0 = __float22half2_rn(make_float2(s[0], s[1]));
        __half2 p1 = __float22half2_rn(make_float2(s[2], s[3]));
        uint2 u;
        u.x = *(unsigned int*)&p0;
        u.y = *(unsigned int*)&p1;
        *((uint2*)(g_Y + (size_t)gr * D) + c4) = u;
    }
}

// ---------------------------------------------------------------------------
// Gather: one warp per node; lane owns 4 columns.  Sums fp16 Y rows in fp32,
// adds c, applies exact GELU, writes the final output row.
// ---------------------------------------------------------------------------
__device__ __forceinline__ float gelu_exact(float x) {
    return 0.5f * x * (1.0f + erff(x * 0.70710678118654752f));
}

__device__ __forceinline__ void acc_row(float4& acc, int s, float w, int lane) {
    uint2 u = __ldg((const uint2*)(g_Y + (size_t)s * D) + lane);
    float2 f01 = __half22float2(*(const __half2*)&u.x);
    float2 f23 = __half22float2(*(const __half2*)&u.y);
    acc.x += w * f01.x; acc.y += w * f01.y;
    acc.z += w * f23.x; acc.w += w * f23.y;
}

__global__ __launch_bounds__(256)
void gather_kernel(float* __restrict__ out, int N) {
    int warp = (int)((blockIdx.x * (unsigned)blockDim.x + threadIdx.x) >> 5);
    int lane = threadIdx.x & 31;
    if (warp >= N) return;

    int cnt = g_cnt[warp];
    int deg = cnt < CAP ? cnt : CAP;
    const int2* lst = g_edge + (size_t)warp * CAP;

    float4 acc = make_float4(0.f, 0.f, 0.f, 0.f);

    int e = 0;
    for (; e + 4 <= deg; e += 4) {
        int4 a = __ldg((const int4*)(lst + e));
        int4 b = __ldg((const int4*)(lst + e) + 1);
        acc_row(acc, a.x, __int_as_float(a.y), lane);
        acc_row(acc, a.z, __int_as_float(a.w), lane);
        acc_row(acc, b.x, __int_as_float(b.y), lane);
        acc_row(acc, b.z, __int_as_float(b.w), lane);
    }
    for (; e < deg; e++) {
        int2 p = __ldg(lst + e);
        acc_row(acc, p.x, __int_as_float(p.y), lane);
    }

    if (cnt > CAP) {   // merge rare overflow contributions (Y-space fp32)
        float4 old = *((const float4*)(g_h + (size_t)warp * D) + lane);
        acc.x += old.x; acc.y += old.y; acc.z += old.z; acc.w += old.w;
    }

    float4 c4 = __ldg((const float4*)g_c + lane);
    float4 o;
    o.x = gelu_exact(acc.x + c4.x);
    o.y = gelu_exact(acc.y + c4.y);
    o.z = gelu_exact(acc.z + c4.z);
    o.w = gelu_exact(acc.w + c4.w);
    *((float4*)(out + (size_t)warp * D) + lane) = o;
}

// ---------------------------------------------------------------------------
extern "C" void kernel_launch(void* const* d_in, const int* in_sizes, int n_in,
                              void* d_out, int out_size) {
    const float* H     = (const float*)d_in[0];
    const int*   src   = (const int*)  d_in[1];
    const int*   dst   = (const int*)  d_in[2];
    const float* ew    = (const float*)d_in[3];
    const float* gamma = (const float*)d_in[4];
    const float* beta  = (const float*)d_in[5];
    const float* mean  = (const float*)d_in[6];
    const float* var   = (const float*)d_in[7];
    const float* W     = (const float*)d_in[8];
    const float* bias  = (const float*)d_in[9];

    int N = in_sizes[0] / D;
    int E = in_sizes[1];

    zero_kernel<<<(N + 255) / 256, 256>>>(N);
    prep_c_kernel<<<1, D>>>(W, bias, gamma, beta, mean, var);

    int smem_bytes = SMEM_BF * 2;            // 71680 B
    cudaFuncSetAttribute(gemm_kernel,
                         cudaFuncAttributeMaxDynamicSharedMemorySize, smem_bytes);
    gemm_kernel<<<(N + BROWS - 1) / BROWS, 256, smem_bytes>>>(H, W, gamma, var, N);

    scatter_kernel<<<(E + 255) / 256, 256>>>(src, dst, ew, E);

    gather_kernel<<<(N * 32 + 255) / 256, 256>>>((float*)d_out, N);
}

// round 10
// speedup vs baseline: 1.6934x; 1.0224x over previous
#include <cuda_runtime.h>
#include <cuda_bf16.h>
#include <cuda_fp16.h>
#include <mma.h>
#include <math.h>
#include <cstdint>

using namespace nvcuda;

#define D 128
#define MAX_N 100096
#define CAP 96
#define BROWS 128
#define PK 64                   // K panel size

// Scratch (allocation-free rule: __device__ globals).
__device__ float   g_h[(size_t)MAX_N * D];      // fp32 accumulator (overflow path only)
__device__ __half  g_Y[(size_t)MAX_N * D];      // Y = H * W' in fp16
__device__ float   g_c[D];                      // c = t.W + b
__device__ int     g_cnt[MAX_N];                // per-node edge count
__device__ int2    g_edge[(size_t)MAX_N * CAP]; // edge buckets (src, w-bits)

// ---------------------------------------------------------------------------
__global__ void zero_kernel(int n) {
    int i = blockIdx.x * blockDim.x + threadIdx.x;
    if (i < n) g_cnt[i] = 0;
}

// c[j] = bias[j] + sum_k (beta_k - mean_k*s_k) * W[k][j]
__global__ void prep_c_kernel(const float* __restrict__ W,
                              const float* __restrict__ bias,
                              const float* __restrict__ gamma,
                              const float* __restrict__ beta,
                              const float* __restrict__ mean,
                              const float* __restrict__ var) {
    int j = threadIdx.x;
    float acc = bias[j];
    for (int k = 0; k < D; k++) {
        float s = gamma[k] * rsqrtf(var[k] + 1e-3f);
        float t = beta[k] - mean[k] * s;
        acc += t * W[k * D + j];
    }
    g_c[j] = acc;
}

// ---------------------------------------------------------------------------
// Scatter: bucket edges by destination.  Overflow (11-sigma unreachable)
// accumulates w*Y[src] directly into g_h (Y-space); gather merges it.
// ---------------------------------------------------------------------------
__global__ void scatter_kernel(const int*   __restrict__ src,
                               const int*   __restrict__ dst,
                               const float* __restrict__ ew,
                               int E) {
    int i = blockIdx.x * blockDim.x + threadIdx.x;
    if (i >= E) return;
    int d = dst[i];
    int pos = atomicAdd(&g_cnt[d], 1);
    int s = src[i];
    float w = ew[i];
    if (pos < CAP) {
        g_edge[(size_t)d * CAP + pos] = make_int2(s, __float_as_int(w));
    } else {
        const __half* yp = g_Y + (size_t)s * D;
        float* o = g_h + (size_t)d * D;
        for (int c = 0; c < D; c += 4) {
            float v0 = __half2float(yp[c + 0]) * w;
            float v1 = __half2float(yp[c + 1]) * w;
            float v2 = __half2float(yp[c + 2]) * w;
            float v3 = __half2float(yp[c + 3]) * w;
            asm volatile("red.global.add.v4.f32 [%0], {%1, %2, %3, %4};"
                         :: "l"(o + c), "f"(v0), "f"(v1), "f"(v2), "f"(v3)
                         : "memory");
        }
    }
}

// ---------------------------------------------------------------------------
// GEMM: Y = H * W'   (bf16x3 tensor-core split), Y stored fp16.
// ---------------------------------------------------------------------------
#define LDA2 72
#define LDW2 136
#define LDWF 136

#define A_HI 0
#define A_LO (A_HI + BROWS * LDA2)
#define W_HI (A_LO + BROWS * LDA2)
#define W_LO (W_HI + PK * LDW2)
#define SMEM_BF (W_LO + PK * LDW2)        // 35840 bf16 = 71680 B

__global__ __launch_bounds__(256, 2)
void gemm_kernel(const float* __restrict__ H,
                 const float* __restrict__ W,
                 const float* __restrict__ gamma,
                 const float* __restrict__ var,
                 int N) {
    extern __shared__ float smf[];
    __nv_bfloat16* smb = (__nv_bfloat16*)smf;
    __shared__ float sS[D];

    int tid  = threadIdx.x;
    if (tid < D) sS[tid] = gamma[tid] * rsqrtf(var[tid] + 1e-3f);

    int row0 = blockIdx.x * BROWS;
    int wid  = tid >> 5;
    int m0   = (wid >> 1) * 32;
    int n0   = (wid & 1) * 64;

    wmma::fragment<wmma::accumulator, 16, 16, 16, float> acc[2][4];
    #pragma unroll
    for (int mf = 0; mf < 2; mf++)
        #pragma unroll
        for (int nf = 0; nf < 4; nf++) wmma::fill_fragment(acc[mf][nf], 0.0f);

    __syncthreads();

    for (int p = 0; p < 2; p++) {
        int k0 = p * PK;

        #pragma unroll
        for (int t = 0; t < 8; t++) {
            int i  = tid + t * 256;
            int r  = i >> 4;
            int c4 = i & 15;
            int gr = row0 + r;
            float4 v = make_float4(0.f, 0.f, 0.f, 0.f);
            if (gr < N) v = __ldg((const float4*)(H + (size_t)gr * D) + (k0 >> 2) + c4);
            __nv_bfloat16 h0 = __float2bfloat16_rn(v.x);
            __nv_bfloat16 h1 = __float2bfloat16_rn(v.y);
            __nv_bfloat16 h2 = __float2bfloat16_rn(v.z);
            __nv_bfloat16 h3 = __float2bfloat16_rn(v.w);
            __nv_bfloat16 l0 = __float2bfloat16_rn(v.x - __bfloat162float(h0));
            __nv_bfloat16 l1 = __float2bfloat16_rn(v.y - __bfloat162float(h1));
            __nv_bfloat16 l2 = __float2bfloat16_rn(v.z - __bfloat162float(h2));
            __nv_bfloat16 l3 = __float2bfloat16_rn(v.w - __bfloat162float(h3));
            int o = r * LDA2 + c4 * 4;
            *(__nv_bfloat162*)(smb + A_HI + o)     = __halves2bfloat162(h0, h1);
            *(__nv_bfloat162*)(smb + A_HI + o + 2) = __halves2bfloat162(h2, h3);
            *(__nv_bfloat162*)(smb + A_LO + o)     = __halves2bfloat162(l0, l1);
            *(__nv_bfloat162*)(smb + A_LO + o + 2) = __halves2bfloat162(l2, l3);
        }

        #pragma unroll
        for (int t = 0; t < 8; t++) {
            int i  = tid + t * 256;
            int k  = i >> 5;
            int c4 = i & 31;
            float sk = sS[k0 + k];
            float4 v = __ldg((const float4*)(W + (size_t)(k0 + k) * D) + c4);
            v.x *= sk; v.y *= sk; v.z *= sk; v.w *= sk;
            __nv_bfloat16 h0 = __float2bfloat16_rn(v.x);
            __nv_bfloat16 h1 = __float2bfloat16_rn(v.y);
            __nv_bfloat16 h2 = __float2bfloat16_rn(v.z);
            __nv_bfloat16 h3 = __float2bfloat16_rn(v.w);
            __nv_bfloat16 l0 = __float2bfloat16_rn(v.x - __bfloat162float(h0));
            __nv_bfloat16 l1 = __float2bfloat16_rn(v.y - __bfloat162float(h1));
            __nv_bfloat16 l2 = __float2bfloat16_rn(v.z - __bfloat162float(h2));
            __nv_bfloat16 l3 = __float2bfloat16_rn(v.w - __bfloat162float(h3));
            int o = k * LDW2 + c4 * 4;
            *(__nv_bfloat162*)(smb + W_HI + o)     = __halves2bfloat162(h0, h1);
            *(__nv_bfloat162*)(smb + W_HI + o + 2) = __halves2bfloat162(h2, h3);
            *(__nv_bfloat162*)(smb + W_LO + o)     = __halves2bfloat162(l0, l1);
            *(__nv_bfloat162*)(smb + W_LO + o + 2) = __halves2bfloat162(l2, l3);
        }
        __syncthreads();

        #pragma unroll
        for (int kk = 0; kk < PK / 16; kk++) {
            wmma::fragment<wmma::matrix_a, 16, 16, 16, __nv_bfloat16, wmma::row_major> aHi[2], aLo[2];
            #pragma unroll
            for (int mf = 0; mf < 2; mf++) {
                wmma::load_matrix_sync(aHi[mf], smb + A_HI + (m0 + mf * 16) * LDA2 + kk * 16, LDA2);
                wmma::load_matrix_sync(aLo[mf], smb + A_LO + (m0 + mf * 16) * LDA2 + kk * 16, LDA2);
            }
            #pragma unroll
            for (int nf = 0; nf < 4; nf++) {
                wmma::fragment<wmma::matrix_b, 16, 16, 16, __nv_bfloat16, wmma::row_major> bHi, bLo;
                wmma::load_matrix_sync(bHi, smb + W_HI + kk * 16 * LDW2 + n0 + nf * 16, LDW2);
                wmma::load_matrix_sync(bLo, smb + W_LO + kk * 16 * LDW2 + n0 + nf * 16, LDW2);
                #pragma unroll
                for (int mf = 0; mf < 2; mf++) {
                    wmma::mma_sync(acc[mf][nf], aHi[mf], bHi, acc[mf][nf]);
                    wmma::mma_sync(acc[mf][nf], aHi[mf], bLo, acc[mf][nf]);
                    wmma::mma_sync(acc[mf][nf], aLo[mf], bHi, acc[mf][nf]);
                }
            }
        }
        __syncthreads();
    }

    #pragma unroll
    for (int mf = 0; mf < 2; mf++)
        #pragma unroll
        for (int nf = 0; nf < 4; nf++)
            wmma::store_matrix_sync(smf + (m0 + mf * 16) * LDWF + n0 + nf * 16,
                                    acc[mf][nf], LDWF, wmma::mem_row_major);
    __syncthreads();

    #pragma unroll
    for (int t = 0; t < 16; t++) {
        int i  = tid + t * 256;
        int r  = i >> 5;
        int c4 = i & 31;
        int gr = row0 + r;
        if (gr >= N) continue;
        const float* s = smf + r * LDWF + c4 * 4;
        __half2 p0 = __float22half2_rn(make_float2(s[0], s[1]));
        __half2 p1 = __float22half2_rn(make_float2(s[2], s[3]));
        uint2 u;
        u.x = *(unsigned int*)&p0;
        u.y = *(unsigned int*)&p1;
        *((uint2*)(g_Y + (size_t)gr * D) + c4) = u;
    }
}

// ---------------------------------------------------------------------------
// Gather: one warp per node; lane owns 4 columns.  Sums fp16 Y rows in fp32,
// adds c, applies exact GELU, writes the final output row.
// ---------------------------------------------------------------------------
__device__ __forceinline__ float gelu_exact(float x) {
    return 0.5f * x * (1.0f + erff(x * 0.70710678118654752f));
}

__device__ __forceinline__ void acc_row(float4& acc, int s, float w, int lane) {
    uint2 u = __ldg((const uint2*)(g_Y + (size_t)s * D) + lane);
    float2 f01 = __half22float2(*(const __half2*)&u.x);
    float2 f23 = __half22float2(*(const __half2*)&u.y);
    acc.x += w * f01.x; acc.y += w * f01.y;
    acc.z += w * f23.x; acc.w += w * f23.y;
}

__global__ __launch_bounds__(256)
void gather_kernel(float* __restrict__ out, int N) {
    int warp = (int)((blockIdx.x * (unsigned)blockDim.x + threadIdx.x) >> 5);
    int lane = threadIdx.x & 31;
    if (warp >= N) return;

    int cnt = g_cnt[warp];
    int deg = cnt < CAP ? cnt : CAP;
    const int2* lst = g_edge + (size_t)warp * CAP;

    float4 acc = make_float4(0.f, 0.f, 0.f, 0.f);

    int e = 0;
    for (; e + 4 <= deg; e += 4) {
        int4 a = __ldg((const int4*)(lst + e));
        int4 b = __ldg((const int4*)(lst + e) + 1);
        acc_row(acc, a.x, __int_as_float(a.y), lane);
        acc_row(acc, a.z, __int_as_float(a.w), lane);
        acc_row(acc, b.x, __int_as_float(b.y), lane);
        acc_row(acc, b.z, __int_as_float(b.w), lane);
    }
    for (; e < deg; e++) {
        int2 p = __ldg(lst + e);
        acc_row(acc, p.x, __int_as_float(p.y), lane);
    }

    if (cnt > CAP) {   // merge rare overflow contributions (Y-space fp32)
        float4 old = *((const float4*)(g_h + (size_t)warp * D) + lane);
        acc.x += old.x; acc.y += old.y; acc.z += old.z; acc.w += old.w;
    }

    float4 c4 = __ldg((const float4*)g_c + lane);
    float4 o;
    o.x = gelu_exact(acc.x + c4.x);
    o.y = gelu_exact(acc.y + c4.y);
    o.z = gelu_exact(acc.z + c4.z);
    o.w = gelu_exact(acc.w + c4.w);
    *((float4*)(out + (size_t)warp * D) + lane) = o;
}

// ---------------------------------------------------------------------------
// Stream fork: scatter (side stream) overlaps gemm (main stream).  Host-side
// stream/event objects are lazily created once; no device memory involved and
// the captured work is identical on every call.
// ---------------------------------------------------------------------------
static cudaStream_t s_side = 0;
static cudaEvent_t  s_e0 = 0, s_e1 = 0;

extern "C" void kernel_launch(void* const* d_in, const int* in_sizes, int n_in,
                              void* d_out, int out_size) {
    const float* H     = (const float*)d_in[0];
    const int*   src   = (const int*)  d_in[1];
    const int*   dst   = (const int*)  d_in[2];
    const float* ew    = (const float*)d_in[3];
    const float* gamma = (const float*)d_in[4];
    const float* beta  = (const float*)d_in[5];
    const float* mean  = (const float*)d_in[6];
    const float* var   = (const float*)d_in[7];
    const float* W     = (const float*)d_in[8];
    const float* bias  = (const float*)d_in[9];

    int N = in_sizes[0] / D;
    int E = in_sizes[1];

    if (s_side == 0) {
        cudaStreamCreateWithFlags(&s_side, cudaStreamNonBlocking);
        cudaEventCreateWithFlags(&s_e0, cudaEventDisableTiming);
        cudaEventCreateWithFlags(&s_e1, cudaEventDisableTiming);
    }

    // Main stream: counters + c vector.
    zero_kernel<<<(N + 255) / 256, 256>>>(N);
    prep_c_kernel<<<1, D>>>(W, bias, gamma, beta, mean, var);

    // Fork: scatter on side stream (independent of gemm).
    cudaEventRecord(s_e0, 0);
    cudaStreamWaitEvent(s_side, s_e0, 0);
    scatter_kernel<<<(E + 255) / 256, 256, 0, s_side>>>(src, dst, ew, E);

    // Main stream: GEMM Y = H * W'.
    int smem_bytes = SMEM_BF * 2;            // 71680 B
    cudaFuncSetAttribute(gemm_kernel,
                         cudaFuncAttributeMaxDynamicSharedMemorySize, smem_bytes);
    gemm_kernel<<<(N + BROWS - 1) / BROWS, 256, smem_bytes>>>(H, W, gamma, var, N);

    // Join: gather needs both gemm (main) and scatter (side).
    cudaEventRecord(s_e1, s_side);
    cudaStreamWaitEvent(0, s_e1, 0);
    gather_kernel<<<(N * 32 + 255) / 256, 256>>>((float*)d_out, N);
}